// round 2
// baseline (speedup 1.0000x reference)
#include <cuda_runtime.h>

// ---------------------------------------------------------------------------
// GatingNeuralAdaptiveBias — register-tiled restructure.
// CTA = 128 pixels (half a (b,i) row), 256 threads.
//   Phase A: per-pixel Fourier + GEMM1(9->64) + silu, both channels in
//            parallel (threads 0-127: ch0, 128-255: ch1) -> H1t[64][256]
//   Phase B: GEMM2 (256 rows x 64 out, K=64) register-tiled 8x8 per thread,
//            f32x2 packed, FiLM fused into store -> Eg[128][128]
//   Phase C: gate GEMM1 (128 rows x 64 out, K=128) tiled 8x4, silu fused
//            -> gh[64][128] (aliases H1t)
//   Phase D: per-pixel gate2 + softmax(2) + fuse + folded LayerNorm dot.
// ---------------------------------------------------------------------------

typedef unsigned long long ull;

#define NTHREADS 256
#define NGRID    4096            // 8*256 rows * 2 halves

// shared memory layout (in floats)
#define OFF_W1   0               // 9*64   = 576
#define OFF_W2   576             // 64*64  = 4096
#define OFF_WG1  4672            // 128*64 = 8192
#define OFF_B1   12864           // 64
#define OFF_B2   12928           // 64
#define OFF_BG1  12992           // 64
#define OFF_WG2  13056           // 64*2 = 128
#define OFF_BG2  13184           // 2 (+2 pad)
#define OFF_FG   13188           // 2*64
#define OFF_FB   13316           // 2*64
#define OFF_C1   13444           // 64 : ln_gamma[k]*Wo[k]
#define OFF_SBW  13508           // 1 (+3 pad)
#define OFF_H1   13512           // 64 x 256 rows (row = ch*128+px); gh aliases
#define OFF_EG   29896           // 128 x 128  (kk = ch*64+out, px)
#define OFF_W2D  46280           // W2 duplicated pairs: 4096 ull = 8192 floats
#define SMEM_FLOATS 54472
#define SMEM_BYTES  (SMEM_FLOATS * 4)   // 217888 B

__device__ __forceinline__ ull pack2(float lo, float hi) {
    ull r;
    asm("mov.b64 %0, {%1, %2};" : "=l"(r) : "f"(lo), "f"(hi));
    return r;
}
__device__ __forceinline__ void unpack2(ull v, float& lo, float& hi) {
    asm("mov.b64 {%0, %1}, %2;" : "=f"(lo), "=f"(hi) : "l"(v));
}
__device__ __forceinline__ void ffma2(ull& d, ull a, ull b) {
    asm("fma.rn.f32x2 %0, %1, %2, %0;" : "+l"(d) : "l"(a), "l"(b));
}
__device__ __forceinline__ float silu_f(float v) {
    return __fdividef(v, 1.0f + __expf(-v));
}

__global__ void __launch_bounds__(NTHREADS, 1)
gnab_kernel(const float* __restrict__ coords,
            const float* __restrict__ cost,
            const float* __restrict__ log_scale,
            const float* __restrict__ W1,  const float* __restrict__ b1,
            const float* __restrict__ W2,  const float* __restrict__ b2,
            const float* __restrict__ fg,  const float* __restrict__ fb,
            const float* __restrict__ Wg1, const float* __restrict__ bg1,
            const float* __restrict__ Wg2, const float* __restrict__ bg2,
            const float* __restrict__ temp,
            const float* __restrict__ lng, const float* __restrict__ lnb,
            const float* __restrict__ Wo,  const float* __restrict__ bo,
            float* __restrict__ out)
{
    extern __shared__ float sm[];
    const int tid = threadIdx.x;

    // ---- cooperative weight staging ----
    for (int t = tid; t < 576;  t += NTHREADS) sm[OFF_W1  + t] = W1[t];
    for (int t = tid; t < 4096; t += NTHREADS) sm[OFF_W2  + t] = W2[t];
    for (int t = tid; t < 8192; t += NTHREADS) sm[OFF_WG1 + t] = Wg1[t];
    {   // duplicated-pair W2 for dup-free f32x2 broadcasts
        ull* w2d = reinterpret_cast<ull*>(&sm[OFF_W2D]);
        for (int t = tid; t < 4096; t += NTHREADS) {
            float w = W2[t];
            w2d[t] = pack2(w, w);
        }
    }
    if (tid < 64) {
        sm[OFF_B1  + tid] = b1[tid];
        sm[OFF_B2  + tid] = b2[tid];
        sm[OFF_BG1 + tid] = bg1[tid];
        sm[OFF_C1  + tid] = lng[tid] * Wo[tid];
    }
    if (tid < 128) {
        sm[OFF_WG2 + tid] = Wg2[tid];
        sm[OFF_FG  + tid] = fg[tid];
        sm[OFF_FB  + tid] = fb[tid];
    }
    if (tid < 2) sm[OFF_BG2 + tid] = bg2[tid];
    if (tid == 0) {
        float s = bo[0];
        for (int k = 0; k < 64; k++) s += lnb[k] * Wo[k];
        sm[OFF_SBW] = s;
    }
    __syncthreads();

    const int cta    = blockIdx.x;      // b*512 + i*2 + half
    const int b      = cta >> 9;
    const int i      = (cta >> 1) & 255;
    const int half   = cta & 1;
    const int pxbase = half * 128;

    // =================== Phase A: Fourier + GEMM1 + silu ===================
    {
        const int ch = tid >> 7;
        const int px = tid & 127;
        const int j  = pxbase + px;

        float x;
        if (ch == 0) {
            x = cost[(b * 256 + i) * 256 + j];
        } else {
            const float dx = coords[(b * 256 + i) * 2 + 0] - coords[(b * 256 + j) * 2 + 0];
            const float dy = coords[(b * 256 + i) * 2 + 1] - coords[(b * 256 + j) * 2 + 1];
            x = atan2f(dy, dx);
        }
        const float sc = __expf(log_scale[ch]);

        float ft[9];
        ft[0] = x * sc;
        #pragma unroll
        for (int q = 0; q < 4; q++) {
            float s, c;
            sincosf(x * (float)(1 << q), &s, &c);
            ft[1 + 2 * q] = s * sc;
            ft[2 + 2 * q] = c * sc;
        }

        ull acc[32];
        {
            const ull* bp = reinterpret_cast<const ull*>(&sm[OFF_B1]);
            #pragma unroll
            for (int m = 0; m < 32; m++) acc[m] = bp[m];
        }
        #pragma unroll
        for (int f = 0; f < 9; f++) {
            const ull fv = pack2(ft[f], ft[f]);
            const ulonglong2* Wv = reinterpret_cast<const ulonglong2*>(&sm[OFF_W1 + f * 64]);
            #pragma unroll
            for (int m = 0; m < 16; m++) {
                ulonglong2 w = Wv[m];
                ffma2(acc[2 * m],     fv, w.x);
                ffma2(acc[2 * m + 1], fv, w.y);
            }
        }
        // silu + transposed store H1t[k][row], row = tid
        float* H = &sm[OFF_H1];
        #pragma unroll
        for (int m = 0; m < 32; m++) {
            float v0, v1;
            unpack2(acc[m], v0, v1);
            H[(2 * m)     * 256 + tid] = silu_f(v0);
            H[(2 * m + 1) * 256 + tid] = silu_f(v1);
        }
    }
    __syncthreads();

    // =================== Phase B: GEMM2 (256 x 64, K=64), 8x8 tiles ========
    {
        const int rb = tid & 31;          // row block: rows rb*8 .. rb*8+7
        const int ob = tid >> 5;          // out block: outs ob*8 .. ob*8+7
        const int ch = rb >> 4;           // channel of this row block

        ull acc[32];                      // acc[p*8+o] = (row 2p, row 2p+1) x out o
        {
            #pragma unroll
            for (int o = 0; o < 8; o++) {
                float bv = sm[OFF_B2 + ob * 8 + o];
                ull bd = pack2(bv, bv);
                acc[o] = bd; acc[8 + o] = bd; acc[16 + o] = bd; acc[24 + o] = bd;
            }
        }

        const float* hp  = &sm[OFF_H1 + rb * 8];
        const ull*   w2d = reinterpret_cast<const ull*>(&sm[OFF_W2D]) + ob * 8;

        #pragma unroll 4
        for (int k = 0; k < 64; k++) {
            const ulonglong2 h01 = *reinterpret_cast<const ulonglong2*>(hp + k * 256);
            const ulonglong2 h23 = *reinterpret_cast<const ulonglong2*>(hp + k * 256 + 4);
            const ulonglong2* wr = reinterpret_cast<const ulonglong2*>(w2d + k * 64);
            ull wk[8];
            {
                ulonglong2 a = wr[0], c = wr[1], d = wr[2], e = wr[3];
                wk[0] = a.x; wk[1] = a.y; wk[2] = c.x; wk[3] = c.y;
                wk[4] = d.x; wk[5] = d.y; wk[6] = e.x; wk[7] = e.y;
            }
            #pragma unroll
            for (int o = 0; o < 8; o++) {
                ffma2(acc[o],      h01.x, wk[o]);
                ffma2(acc[8 + o],  h01.y, wk[o]);
                ffma2(acc[16 + o], h23.x, wk[o]);
                ffma2(acc[24 + o], h23.y, wk[o]);
            }
        }

        // FiLM + store Eg[kk][px], px pairs packed as 8B stores
        float g[8], be[8];
        #pragma unroll
        for (int o = 0; o < 8; o++) {
            g[o]  = sm[OFF_FG + ch * 64 + ob * 8 + o];
            be[o] = sm[OFF_FB + ch * 64 + ob * 8 + o];
        }
        #pragma unroll
        for (int p = 0; p < 4; p++) {
            const int row = rb * 8 + 2 * p;
            const int px  = row & 127;
            #pragma unroll
            for (int o = 0; o < 8; o++) {
                float c0, c1;
                unpack2(acc[p * 8 + o], c0, c1);
                const float e0 = c0 * g[o] + be[o];
                const float e1 = c1 * g[o] + be[o];
                const int kk = ch * 64 + ob * 8 + o;
                *reinterpret_cast<ull*>(&sm[OFF_EG + kk * 128 + px]) = pack2(e0, e1);
            }
        }
    }
    __syncthreads();

    // =================== Phase C: gate GEMM1 (128 x 64, K=128), 8x4 ========
    {
        const int rb = tid & 15;          // px block: px rb*8 .. rb*8+7
        const int ob = tid >> 4;          // out block: outs ob*4 .. ob*4+3

        ull acc[16];                      // acc[p*4+o]
        {
            #pragma unroll
            for (int o = 0; o < 4; o++) {
                float bv = sm[OFF_BG1 + ob * 4 + o];
                ull bd = pack2(bv, bv);
                acc[o] = bd; acc[4 + o] = bd; acc[8 + o] = bd; acc[12 + o] = bd;
            }
        }

        const float* ep = &sm[OFF_EG + rb * 8];

        #pragma unroll 4
        for (int k = 0; k < 128; k++) {
            const ulonglong2 e01 = *reinterpret_cast<const ulonglong2*>(ep + k * 128);
            const ulonglong2 e23 = *reinterpret_cast<const ulonglong2*>(ep + k * 128 + 4);
            const float4 wv = *reinterpret_cast<const float4*>(&sm[OFF_WG1 + k * 64 + ob * 4]);
            ull wd[4];
            wd[0] = pack2(wv.x, wv.x);
            wd[1] = pack2(wv.y, wv.y);
            wd[2] = pack2(wv.z, wv.z);
            wd[3] = pack2(wv.w, wv.w);
            #pragma unroll
            for (int o = 0; o < 4; o++) {
                ffma2(acc[o],      e01.x, wd[o]);
                ffma2(acc[4 + o],  e01.y, wd[o]);
                ffma2(acc[8 + o],  e23.x, wd[o]);
                ffma2(acc[12 + o], e23.y, wd[o]);
            }
        }

        // silu + store gh[out][px] (aliases H1 region)
        #pragma unroll
        for (int p = 0; p < 4; p++) {
            const int px = rb * 8 + 2 * p;
            #pragma unroll
            for (int o = 0; o < 4; o++) {
                float c0, c1;
                unpack2(acc[p * 4 + o], c0, c1);
                const int kk = ob * 4 + o;
                *reinterpret_cast<ull*>(&sm[OFF_H1 + kk * 128 + px]) =
                    pack2(silu_f(c0), silu_f(c1));
            }
        }
    }
    __syncthreads();

    // =================== Phase D: gate2 + softmax + fuse + LN ==============
    if (tid < 128) {
        const int px = tid;
        const float itemp = __expf(-temp[0]);

        float l0 = sm[OFF_BG2];
        float l1 = sm[OFF_BG2 + 1];
        #pragma unroll 8
        for (int k = 0; k < 64; k++) {
            const float gv = sm[OFF_H1 + k * 128 + px];
            l0 += gv * sm[OFF_WG2 + 2 * k];
            l1 += gv * sm[OFF_WG2 + 2 * k + 1];
        }
        const float dlt = (l0 - l1) * itemp;
        const float w0  = __fdividef(1.0f, 1.0f + __expf(-dlt));
        const float w1  = 1.0f - w0;

        float fv[64];
        float fsum = 0.0f;
        #pragma unroll
        for (int k = 0; k < 64; k++) {
            fv[k] = w0 * sm[OFF_EG + k * 128 + px]
                  + w1 * sm[OFF_EG + (64 + k) * 128 + px];
            fsum += fv[k];
        }
        const float mu = fsum * (1.0f / 64.0f);

        float var = 0.0f, dot = 0.0f;
        #pragma unroll
        for (int k = 0; k < 64; k++) {
            const float f = fv[k] - mu;
            var += f * f;
            dot += f * sm[OFF_C1 + k];
        }
        const float rstd = rsqrtf(var * (1.0f / 64.0f) + 1e-5f);

        out[(b * 256 + i) * 256 + pxbase + px] = dot * rstd + sm[OFF_SBW];
    }
}

extern "C" void kernel_launch(void* const* d_in, const int* in_sizes, int n_in,
                              void* d_out, int out_size)
{
    const float* coords = (const float*)d_in[0];
    const float* cost   = (const float*)d_in[1];
    const float* lsc    = (const float*)d_in[2];
    const float* W1     = (const float*)d_in[3];
    const float* b1     = (const float*)d_in[4];
    const float* W2     = (const float*)d_in[5];
    const float* b2     = (const float*)d_in[6];
    const float* fg     = (const float*)d_in[7];
    const float* fb     = (const float*)d_in[8];
    const float* Wg1    = (const float*)d_in[9];
    const float* bg1    = (const float*)d_in[10];
    const float* Wg2    = (const float*)d_in[11];
    const float* bg2    = (const float*)d_in[12];
    const float* temp   = (const float*)d_in[13];
    const float* lng    = (const float*)d_in[14];
    const float* lnb    = (const float*)d_in[15];
    const float* Wo     = (const float*)d_in[16];
    const float* bo     = (const float*)d_in[17];
    float* out          = (float*)d_out;

    cudaFuncSetAttribute(gnab_kernel,
                         cudaFuncAttributeMaxDynamicSharedMemorySize,
                         SMEM_BYTES);

    gnab_kernel<<<NGRID, NTHREADS, SMEM_BYTES>>>(
        coords, cost, lsc, W1, b1, W2, b2, fg, fb,
        Wg1, bg1, Wg2, bg2, temp, lng, lnb, Wo, bo, out);
}

// round 3
// speedup vs baseline: 1.2699x; 1.2699x over previous
#include <cuda_runtime.h>
#include <math.h>

// ---------------------------------------------------------------------------
// GatingNeuralAdaptiveBias — streaming thread-per-pixel, zero activation smem.
//
// Folds (precomputed once per launch in a setup kernel):
//   Wc_ch[j][o]  = sum_k W2[j][k] * gamma_ch[k] * Wg1[ch*64+k][o]   (gate from h1)
//   W2g_ch[j][k] = W2[j][k] * gamma_ch[k]                           (FiLM into W2)
//   bgc[o]       = bg1[o] + sum_k (b2*g0+B0)[k] Wg1[k][o] + (b2*g1+B1)[k] Wg1[64+k][o]
//   eb_ch[k]     = b2[k]*gamma_ch[k] + beta_ch[k]
//   c1[k]        = ln_gamma[k]*Wo[k];  sbw = sum(ln_beta*Wo)+bo
//
// Main kernel per thread (one pixel):
//   ft0/ft1 -> gate: stream h_ch[j], gacc += h*Wc_ch[j][:]  -> w0
//           -> fused: stream h_ch[j] again, facc += (w_ch*h)*W2g_ch[j][:]
//           -> mean/var/dot reductions on facc -> out.
// All smem loads are warp-uniform broadcasts; no __syncthreads after staging.
// ---------------------------------------------------------------------------

typedef unsigned long long ull;

#define P_W1T   0        // 64 x 12 : [b1[j], W1t[j][0..8], pad, pad]
#define P_WC    768      // 2 x 64 x 64
#define P_W2G   8960     // 2 x 64 x 64
#define P_BGC   17152    // 64
#define P_EB    17216    // 2 x 64
#define P_WG2   17344    // 64 x 2
#define P_C1    17472    // 64
#define P_SC    17536    // scalars
#define PRE_FLOATS 17552
#define SMEM_BYTES (PRE_FLOATS * 4)   // 70208 B

__device__ __align__(16) float g_pre[PRE_FLOATS];

__device__ __forceinline__ ull pack2(float lo, float hi) {
    ull r;
    asm("mov.b64 %0, {%1, %2};" : "=l"(r) : "f"(lo), "f"(hi));
    return r;
}
__device__ __forceinline__ void unpack2(ull v, float& lo, float& hi) {
    asm("mov.b64 {%0, %1}, %2;" : "=f"(lo), "=f"(hi) : "l"(v));
}
__device__ __forceinline__ void ffma2(ull& d, ull a, ull b) {
    asm("fma.rn.f32x2 %0, %1, %2, %0;" : "+l"(d) : "l"(a), "l"(b));
}
__device__ __forceinline__ float silu_f(float v) {
    return __fdividef(v, 1.0f + __expf(-v));
}

// ============================ setup kernel =================================
__global__ void gnab_precompute(const float* __restrict__ log_scale,
                                const float* __restrict__ W1,  const float* __restrict__ b1,
                                const float* __restrict__ W2,  const float* __restrict__ b2,
                                const float* __restrict__ fg,  const float* __restrict__ fb,
                                const float* __restrict__ Wg1, const float* __restrict__ bg1,
                                const float* __restrict__ Wg2, const float* __restrict__ bg2,
                                const float* __restrict__ temp,
                                const float* __restrict__ lng, const float* __restrict__ lnb,
                                const float* __restrict__ Wo,  const float* __restrict__ bo)
{
    const int tid = threadIdx.x;          // 128 threads
    const int bl  = blockIdx.x;           // 64 blocks
    const int ch  = bl >> 5;
    const int jj  = ((bl & 31) << 1) + (tid >> 6);
    const int o   = tid & 63;

    // Wc[ch][jj][o]
    float acc = 0.0f;
    #pragma unroll 4
    for (int k = 0; k < 64; k++) {
        const float w = W2[jj * 64 + k] * fg[ch * 64 + k];
        acc = fmaf(w, Wg1[(ch * 64 + k) * 64 + o], acc);
    }
    g_pre[P_WC + ch * 4096 + jj * 64 + o] = acc;

    // W2g[ch][jj][k]  (o plays role of k)
    g_pre[P_W2G + ch * 4096 + jj * 64 + o] = W2[jj * 64 + o] * fg[ch * 64 + o];

    if (bl == 0) {
        if (tid < 64) {
            float* row = &g_pre[P_W1T + tid * 12];
            row[0] = b1[tid];
            #pragma unroll
            for (int f = 0; f < 9; f++) row[1 + f] = W1[f * 64 + tid];
            row[10] = 0.0f; row[11] = 0.0f;

            g_pre[P_C1 + tid] = lng[tid] * Wo[tid];

            float a = bg1[tid];
            #pragma unroll 4
            for (int k = 0; k < 64; k++) {
                a = fmaf(b2[k] * fg[k]      + fb[k],      Wg1[k * 64 + tid],        a);
                a = fmaf(b2[k] * fg[64 + k] + fb[64 + k], Wg1[(64 + k) * 64 + tid], a);
            }
            g_pre[P_BGC + tid] = a;
        }
        if (tid < 128) {
            const int c = tid >> 6, k = tid & 63;
            g_pre[P_EB + tid]  = b2[k] * fg[c * 64 + k] + fb[c * 64 + k];
            g_pre[P_WG2 + tid] = Wg2[tid];
        }
        if (tid == 0) {
            g_pre[P_SC + 0] = expf(log_scale[0]);
            g_pre[P_SC + 1] = expf(log_scale[1]);
            g_pre[P_SC + 2] = expf(-temp[0]);
            float s = bo[0];
            for (int k = 0; k < 64; k++) s += lnb[k] * Wo[k];
            g_pre[P_SC + 3] = s;                // sbw
            g_pre[P_SC + 4] = bg2[0];
            g_pre[P_SC + 5] = bg2[1];
            g_pre[P_SC + 6] = 0.0f;
            g_pre[P_SC + 7] = 0.0f;
        }
    }
}

// ============================ main kernel ==================================

// stream h_ch[j] and accumulate acc[0:32] (64 outs) += (wscale*silu(h)) * wmat[j][:]
__device__ __forceinline__ void enc_pass(const float* __restrict__ w1t,
                                         const float* __restrict__ wmat,
                                         const float ft[9], float wscale,
                                         ull acc[32])
{
    #pragma unroll 4
    for (int jj = 0; jj < 64; jj++) {
        const float4* r = reinterpret_cast<const float4*>(&w1t[jj * 12]);
        const float4 a = r[0], bq = r[1], c = r[2];
        float h = a.x;
        h = fmaf(ft[0], a.y,  h);
        h = fmaf(ft[1], a.z,  h);
        h = fmaf(ft[2], a.w,  h);
        h = fmaf(ft[3], bq.x, h);
        h = fmaf(ft[4], bq.y, h);
        h = fmaf(ft[5], bq.z, h);
        h = fmaf(ft[6], bq.w, h);
        h = fmaf(ft[7], c.x,  h);
        h = fmaf(ft[8], c.y,  h);
        h = wscale * silu_f(h);
        const ull hh = pack2(h, h);
        const ulonglong2* W = reinterpret_cast<const ulonglong2*>(&wmat[jj * 64]);
        #pragma unroll
        for (int m = 0; m < 16; m++) {
            const ulonglong2 wv = W[m];
            ffma2(acc[2 * m],     hh, wv.x);
            ffma2(acc[2 * m + 1], hh, wv.y);
        }
    }
}

__global__ void __launch_bounds__(256, 2)
gnab_main(const float* __restrict__ coords,
          const float* __restrict__ cost,
          float* __restrict__ out)
{
    extern __shared__ float sm[];
    const int tid = threadIdx.x;

    {   // stage all precomputed weights (16B copies)
        const float4* src = reinterpret_cast<const float4*>(g_pre);
        float4* dst = reinterpret_cast<float4*>(sm);
        #pragma unroll 4
        for (int t = tid; t < PRE_FLOATS / 4; t += 256) dst[t] = src[t];
    }
    __syncthreads();

    const int bi    = blockIdx.x;          // b*256 + i
    const int b     = bi >> 8;
    const int i     = bi & 255;
    const int j     = tid;
    const int pixel = bi * 256 + j;

    const float scl0  = sm[P_SC + 0];
    const float scl1  = sm[P_SC + 1];
    const float itemp = sm[P_SC + 2];
    const float sbw   = sm[P_SC + 3];

    const float x0 = cost[pixel];
    const float dx = coords[(b * 256 + i) * 2 + 0] - coords[(b * 256 + j) * 2 + 0];
    const float dy = coords[(b * 256 + i) * 2 + 1] - coords[(b * 256 + j) * 2 + 1];
    const float x1 = atan2f(dy, dx);

    float ft0[9], ft1[9];
    ft0[0] = x0 * scl0;
    ft1[0] = x1 * scl1;
    #pragma unroll
    for (int q = 0; q < 4; q++) {
        float s, c;
        sincosf(x0 * (float)(1 << q), &s, &c);
        ft0[1 + 2 * q] = s * scl0;
        ft0[2 + 2 * q] = c * scl0;
        sincosf(x1 * (float)(1 << q), &s, &c);
        ft1[1 + 2 * q] = s * scl1;
        ft1[2 + 2 * q] = c * scl1;
    }

    // ---------------- phase 1: gate (from h1 via folded Wc) ----------------
    ull gacc[32];
    {
        const ull* bp = reinterpret_cast<const ull*>(&sm[P_BGC]);
        #pragma unroll
        for (int m = 0; m < 32; m++) gacc[m] = bp[m];
    }
    enc_pass(&sm[P_W1T], &sm[P_WC],        ft0, 1.0f, gacc);
    enc_pass(&sm[P_W1T], &sm[P_WC + 4096], ft1, 1.0f, gacc);

    float l0 = sm[P_SC + 4];
    float l1 = sm[P_SC + 5];
    {
        const float2* wg2 = reinterpret_cast<const float2*>(&sm[P_WG2]);
        #pragma unroll
        for (int m = 0; m < 32; m++) {
            float v0, v1;
            unpack2(gacc[m], v0, v1);
            v0 = silu_f(v0);
            v1 = silu_f(v1);
            const float2 wa = wg2[2 * m];
            const float2 wb = wg2[2 * m + 1];
            l0 = fmaf(v0, wa.x, fmaf(v1, wb.x, l0));
            l1 = fmaf(v0, wa.y, fmaf(v1, wb.y, l1));
        }
    }
    const float dlt = (l0 - l1) * itemp;
    const float w0  = __fdividef(1.0f, 1.0f + __expf(-dlt));
    const float w1  = 1.0f - w0;

    // ---------------- phase 2: fused = w0*e0 + w1*e1 (direct) ---------------
    ull facc[32];
    {
        const float* eb0 = &sm[P_EB];
        const float* eb1 = &sm[P_EB + 64];
        #pragma unroll
        for (int m = 0; m < 32; m++) {
            const float f0 = fmaf(w0, eb0[2 * m],     w1 * eb1[2 * m]);
            const float f1 = fmaf(w0, eb0[2 * m + 1], w1 * eb1[2 * m + 1]);
            facc[m] = pack2(f0, f1);
        }
    }
    enc_pass(&sm[P_W1T], &sm[P_W2G],        ft0, w0, facc);
    enc_pass(&sm[P_W1T], &sm[P_W2G + 4096], ft1, w1, facc);

    // ---------------- epilogue: LN + output dot (folded) --------------------
    float s = 0.0f;
    #pragma unroll
    for (int m = 0; m < 32; m++) {
        float v0, v1;
        unpack2(facc[m], v0, v1);
        s += v0 + v1;
    }
    const float mu = s * (1.0f / 64.0f);

    float var = 0.0f, dot = 0.0f;
    const float* c1 = &sm[P_C1];
    #pragma unroll
    for (int m = 0; m < 32; m++) {
        float v0, v1;
        unpack2(facc[m], v0, v1);
        const float f0 = v0 - mu;
        const float f1 = v1 - mu;
        var = fmaf(f0, f0, fmaf(f1, f1, var));
        dot = fmaf(f0, c1[2 * m], fmaf(f1, c1[2 * m + 1], dot));
    }
    const float rstd = rsqrtf(var * (1.0f / 64.0f) + 1e-5f);

    out[pixel] = fmaf(dot, rstd, sbw);
}

// ============================ launch =======================================
extern "C" void kernel_launch(void* const* d_in, const int* in_sizes, int n_in,
                              void* d_out, int out_size)
{
    const float* coords = (const float*)d_in[0];
    const float* cost   = (const float*)d_in[1];
    const float* lsc    = (const float*)d_in[2];
    const float* W1     = (const float*)d_in[3];
    const float* b1     = (const float*)d_in[4];
    const float* W2     = (const float*)d_in[5];
    const float* b2     = (const float*)d_in[6];
    const float* fg     = (const float*)d_in[7];
    const float* fb     = (const float*)d_in[8];
    const float* Wg1    = (const float*)d_in[9];
    const float* bg1    = (const float*)d_in[10];
    const float* Wg2    = (const float*)d_in[11];
    const float* bg2    = (const float*)d_in[12];
    const float* temp   = (const float*)d_in[13];
    const float* lng    = (const float*)d_in[14];
    const float* lnb    = (const float*)d_in[15];
    const float* Wo     = (const float*)d_in[16];
    const float* bo     = (const float*)d_in[17];
    float* out          = (float*)d_out;

    cudaFuncSetAttribute(gnab_main,
                         cudaFuncAttributeMaxDynamicSharedMemorySize,
                         SMEM_BYTES);

    gnab_precompute<<<64, 128>>>(lsc, W1, b1, W2, b2, fg, fb,
                                 Wg1, bg1, Wg2, bg2, temp, lng, lnb, Wo, bo);
    gnab_main<<<2048, 256, SMEM_BYTES>>>(coords, cost, out);
}

// round 4
// speedup vs baseline: 1.4430x; 1.1363x over previous
#include <cuda_runtime.h>
#include <math.h>

// ---------------------------------------------------------------------------
// GatingNeuralAdaptiveBias — streaming, 2 pixels per thread (weight-LDS
// amortized 2x). CTA = 2 adjacent rows (i, i+1) of one batch; thread t
// handles column j=t in both rows. Folded weights as in R3:
//   Wc_ch  = W2 diag(gamma_ch) Wg1_half   (gate straight from h1)
//   W2g_ch = W2 diag(gamma_ch)            (FiLM folded)
//   LN folded into c1 = ln_gamma*Wo, sbw = sum(ln_beta*Wo)+bo.
// ---------------------------------------------------------------------------

typedef unsigned long long ull;

#define P_W1T   0        // 64 x 12 : [b1[j], W1t[j][0..8], pad, pad]
#define P_WC    768      // 2 x 64 x 64
#define P_W2G   8960     // 2 x 64 x 64
#define P_BGC   17152    // 64
#define P_EB    17216    // 2 x 64
#define P_WG2   17344    // 64 x 2
#define P_C1    17472    // 64
#define P_SC    17536    // scalars
#define PRE_FLOATS 17552
#define SMEM_BYTES (PRE_FLOATS * 4)   // 70208 B

__device__ __align__(16) float g_pre[PRE_FLOATS];

__device__ __forceinline__ ull pack2(float lo, float hi) {
    ull r;
    asm("mov.b64 %0, {%1, %2};" : "=l"(r) : "f"(lo), "f"(hi));
    return r;
}
__device__ __forceinline__ void unpack2(ull v, float& lo, float& hi) {
    asm("mov.b64 {%0, %1}, %2;" : "=f"(lo), "=f"(hi) : "l"(v));
}
__device__ __forceinline__ void ffma2(ull& d, ull a, ull b) {
    asm("fma.rn.f32x2 %0, %1, %2, %0;" : "+l"(d) : "l"(a), "l"(b));
}
__device__ __forceinline__ float silu_f(float v) {
    return __fdividef(v, 1.0f + __expf(-v));
}

// ============================ setup kernel =================================
__global__ void gnab_precompute(const float* __restrict__ log_scale,
                                const float* __restrict__ W1,  const float* __restrict__ b1,
                                const float* __restrict__ W2,  const float* __restrict__ b2,
                                const float* __restrict__ fg,  const float* __restrict__ fb,
                                const float* __restrict__ Wg1, const float* __restrict__ bg1,
                                const float* __restrict__ Wg2, const float* __restrict__ bg2,
                                const float* __restrict__ temp,
                                const float* __restrict__ lng, const float* __restrict__ lnb,
                                const float* __restrict__ Wo,  const float* __restrict__ bo)
{
    const int tid = threadIdx.x;          // 128 threads
    const int bl  = blockIdx.x;           // 64 blocks
    const int ch  = bl >> 5;
    const int jj  = ((bl & 31) << 1) + (tid >> 6);
    const int o   = tid & 63;

    // Wc[ch][jj][o]
    float acc = 0.0f;
    #pragma unroll 4
    for (int k = 0; k < 64; k++) {
        const float w = W2[jj * 64 + k] * fg[ch * 64 + k];
        acc = fmaf(w, Wg1[(ch * 64 + k) * 64 + o], acc);
    }
    g_pre[P_WC + ch * 4096 + jj * 64 + o] = acc;

    // W2g[ch][jj][k]  (o plays role of k)
    g_pre[P_W2G + ch * 4096 + jj * 64 + o] = W2[jj * 64 + o] * fg[ch * 64 + o];

    if (bl == 0) {
        if (tid < 64) {
            float* row = &g_pre[P_W1T + tid * 12];
            row[0] = b1[tid];
            #pragma unroll
            for (int f = 0; f < 9; f++) row[1 + f] = W1[f * 64 + tid];
            row[10] = 0.0f; row[11] = 0.0f;

            g_pre[P_C1 + tid] = lng[tid] * Wo[tid];

            float a = bg1[tid];
            #pragma unroll 4
            for (int k = 0; k < 64; k++) {
                a = fmaf(b2[k] * fg[k]      + fb[k],      Wg1[k * 64 + tid],        a);
                a = fmaf(b2[k] * fg[64 + k] + fb[64 + k], Wg1[(64 + k) * 64 + tid], a);
            }
            g_pre[P_BGC + tid] = a;
        }
        if (tid < 128) {
            const int c = tid >> 6, k = tid & 63;
            g_pre[P_EB + tid]  = b2[k] * fg[c * 64 + k] + fb[c * 64 + k];
            g_pre[P_WG2 + tid] = Wg2[tid];
        }
        if (tid == 0) {
            g_pre[P_SC + 0] = expf(log_scale[0]);
            g_pre[P_SC + 1] = expf(log_scale[1]);
            g_pre[P_SC + 2] = expf(-temp[0]);
            float s = bo[0];
            for (int k = 0; k < 64; k++) s += lnb[k] * Wo[k];
            g_pre[P_SC + 3] = s;                // sbw
            g_pre[P_SC + 4] = bg2[0];
            g_pre[P_SC + 5] = bg2[1];
            g_pre[P_SC + 6] = 0.0f;
            g_pre[P_SC + 7] = 0.0f;
        }
    }
}

// ============================ main kernel ==================================

// stream h[jj] for TWO pixels; weights loaded once, fed to both acc sets.
__device__ __forceinline__ void enc_pass2(const float* __restrict__ w1t,
                                          const float* __restrict__ wmat,
                                          const float ftA[9], const float ftB[9],
                                          float wsA, float wsB,
                                          ull accA[32], ull accB[32])
{
    #pragma unroll 2
    for (int jj = 0; jj < 64; jj++) {
        const float4* r = reinterpret_cast<const float4*>(&w1t[jj * 12]);
        const float4 a = r[0], bq = r[1], c = r[2];

        float hA = a.x, hB = a.x;
        hA = fmaf(ftA[0], a.y,  hA);  hB = fmaf(ftB[0], a.y,  hB);
        hA = fmaf(ftA[1], a.z,  hA);  hB = fmaf(ftB[1], a.z,  hB);
        hA = fmaf(ftA[2], a.w,  hA);  hB = fmaf(ftB[2], a.w,  hB);
        hA = fmaf(ftA[3], bq.x, hA);  hB = fmaf(ftB[3], bq.x, hB);
        hA = fmaf(ftA[4], bq.y, hA);  hB = fmaf(ftB[4], bq.y, hB);
        hA = fmaf(ftA[5], bq.z, hA);  hB = fmaf(ftB[5], bq.z, hB);
        hA = fmaf(ftA[6], bq.w, hA);  hB = fmaf(ftB[6], bq.w, hB);
        hA = fmaf(ftA[7], c.x,  hA);  hB = fmaf(ftB[7], c.x,  hB);
        hA = fmaf(ftA[8], c.y,  hA);  hB = fmaf(ftB[8], c.y,  hB);
        hA = wsA * silu_f(hA);
        hB = wsB * silu_f(hB);
        const ull hhA = pack2(hA, hA);
        const ull hhB = pack2(hB, hB);

        const ulonglong2* W = reinterpret_cast<const ulonglong2*>(&wmat[jj * 64]);
        #pragma unroll
        for (int m = 0; m < 16; m++) {
            const ulonglong2 wv = W[m];
            ffma2(accA[2 * m],     hhA, wv.x);
            ffma2(accA[2 * m + 1], hhA, wv.y);
            ffma2(accB[2 * m],     hhB, wv.x);
            ffma2(accB[2 * m + 1], hhB, wv.y);
        }
    }
}

__global__ void __launch_bounds__(256, 1)
gnab_main(const float* __restrict__ coords,
          const float* __restrict__ cost,
          float* __restrict__ out)
{
    extern __shared__ float sm[];
    const int tid = threadIdx.x;

    {   // stage all precomputed weights (16B copies)
        const float4* src = reinterpret_cast<const float4*>(g_pre);
        float4* dst = reinterpret_cast<float4*>(sm);
        #pragma unroll 4
        for (int t = tid; t < PRE_FLOATS / 4; t += 256) dst[t] = src[t];
    }
    __syncthreads();

    const int cta = blockIdx.x;            // covers rows 2*cta, 2*cta+1
    const int r0  = cta * 2;
    const int b   = r0 >> 8;
    const int i0  = r0 & 255;
    const int j   = tid;
    const int pxA = r0 * 256 + j;          // (b, i0,   j)
    const int pxB = pxA + 256;             // (b, i0+1, j)

    const float scl0  = sm[P_SC + 0];
    const float scl1  = sm[P_SC + 1];
    const float itemp = sm[P_SC + 2];
    const float sbw   = sm[P_SC + 3];

    // inputs
    const float xA0 = cost[pxA];
    const float xB0 = cost[pxB];
    const float cjx = coords[(b * 256 + j) * 2 + 0];
    const float cjy = coords[(b * 256 + j) * 2 + 1];
    const float xA1 = atan2f(coords[(b * 256 + i0) * 2 + 1] - cjy,
                             coords[(b * 256 + i0) * 2 + 0] - cjx);
    const float xB1 = atan2f(coords[(b * 256 + i0 + 1) * 2 + 1] - cjy,
                             coords[(b * 256 + i0 + 1) * 2 + 0] - cjx);

    float ftA0[9], ftA1[9], ftB0[9], ftB1[9];
    ftA0[0] = xA0 * scl0;  ftA1[0] = xA1 * scl1;
    ftB0[0] = xB0 * scl0;  ftB1[0] = xB1 * scl1;
    #pragma unroll
    for (int q = 0; q < 4; q++) {
        float s, c;
        sincosf(xA0 * (float)(1 << q), &s, &c);
        ftA0[1 + 2 * q] = s * scl0;  ftA0[2 + 2 * q] = c * scl0;
        sincosf(xA1 * (float)(1 << q), &s, &c);
        ftA1[1 + 2 * q] = s * scl1;  ftA1[2 + 2 * q] = c * scl1;
        sincosf(xB0 * (float)(1 << q), &s, &c);
        ftB0[1 + 2 * q] = s * scl0;  ftB0[2 + 2 * q] = c * scl0;
        sincosf(xB1 * (float)(1 << q), &s, &c);
        ftB1[1 + 2 * q] = s * scl1;  ftB1[2 + 2 * q] = c * scl1;
    }

    // ---------------- phase 1: gate (folded Wc) -----------------------------
    ull gaccA[32], gaccB[32];
    {
        const ull* bp = reinterpret_cast<const ull*>(&sm[P_BGC]);
        #pragma unroll
        for (int m = 0; m < 32; m++) { gaccA[m] = bp[m]; gaccB[m] = bp[m]; }
    }
    enc_pass2(&sm[P_W1T], &sm[P_WC],        ftA0, ftB0, 1.0f, 1.0f, gaccA, gaccB);
    enc_pass2(&sm[P_W1T], &sm[P_WC + 4096], ftA1, ftB1, 1.0f, 1.0f, gaccA, gaccB);

    float l0A = sm[P_SC + 4], l1A = sm[P_SC + 5];
    float l0B = l0A,          l1B = l1A;
    {
        const float2* wg2 = reinterpret_cast<const float2*>(&sm[P_WG2]);
        #pragma unroll
        for (int m = 0; m < 32; m++) {
            const float2 wa = wg2[2 * m];
            const float2 wb = wg2[2 * m + 1];
            float v0, v1;
            unpack2(gaccA[m], v0, v1);
            v0 = silu_f(v0); v1 = silu_f(v1);
            l0A = fmaf(v0, wa.x, fmaf(v1, wb.x, l0A));
            l1A = fmaf(v0, wa.y, fmaf(v1, wb.y, l1A));
            unpack2(gaccB[m], v0, v1);
            v0 = silu_f(v0); v1 = silu_f(v1);
            l0B = fmaf(v0, wa.x, fmaf(v1, wb.x, l0B));
            l1B = fmaf(v0, wa.y, fmaf(v1, wb.y, l1B));
        }
    }
    const float w0A = __fdividef(1.0f, 1.0f + __expf(-(l0A - l1A) * itemp));
    const float w1A = 1.0f - w0A;
    const float w0B = __fdividef(1.0f, 1.0f + __expf(-(l0B - l1B) * itemp));
    const float w1B = 1.0f - w0B;

    // ---------------- phase 2: fused = w0*e0 + w1*e1 (direct) ---------------
    ull faccA[32], faccB[32];
    {
        const float* eb0 = &sm[P_EB];
        const float* eb1 = &sm[P_EB + 64];
        #pragma unroll
        for (int m = 0; m < 32; m++) {
            const float e0a = eb0[2 * m], e0b = eb0[2 * m + 1];
            const float e1a = eb1[2 * m], e1b = eb1[2 * m + 1];
            faccA[m] = pack2(fmaf(w0A, e0a, w1A * e1a), fmaf(w0A, e0b, w1A * e1b));
            faccB[m] = pack2(fmaf(w0B, e0a, w1B * e1a), fmaf(w0B, e0b, w1B * e1b));
        }
    }
    enc_pass2(&sm[P_W1T], &sm[P_W2G],        ftA0, ftB0, w0A, w0B, faccA, faccB);
    enc_pass2(&sm[P_W1T], &sm[P_W2G + 4096], ftA1, ftB1, w1A, w1B, faccA, faccB);

    // ---------------- epilogue: LN + output dot (folded) --------------------
    const float* c1 = &sm[P_C1];

    float sA = 0.0f, sB = 0.0f;
    #pragma unroll
    for (int m = 0; m < 32; m++) {
        float v0, v1;
        unpack2(faccA[m], v0, v1); sA += v0 + v1;
        unpack2(faccB[m], v0, v1); sB += v0 + v1;
    }
    const float muA = sA * (1.0f / 64.0f);
    const float muB = sB * (1.0f / 64.0f);

    float varA = 0.0f, dotA = 0.0f, varB = 0.0f, dotB = 0.0f;
    #pragma unroll
    for (int m = 0; m < 32; m++) {
        const float ca = c1[2 * m], cb = c1[2 * m + 1];
        float v0, v1;
        unpack2(faccA[m], v0, v1);
        { const float f0 = v0 - muA, f1 = v1 - muA;
          varA = fmaf(f0, f0, fmaf(f1, f1, varA));
          dotA = fmaf(f0, ca, fmaf(f1, cb, dotA)); }
        unpack2(faccB[m], v0, v1);
        { const float f0 = v0 - muB, f1 = v1 - muB;
          varB = fmaf(f0, f0, fmaf(f1, f1, varB));
          dotB = fmaf(f0, ca, fmaf(f1, cb, dotB)); }
    }
    const float rstdA = rsqrtf(varA * (1.0f / 64.0f) + 1e-5f);
    const float rstdB = rsqrtf(varB * (1.0f / 64.0f) + 1e-5f);

    out[pxA] = fmaf(dotA, rstdA, sbw);
    out[pxB] = fmaf(dotB, rstdB, sbw);
}

// ============================ launch =======================================
extern "C" void kernel_launch(void* const* d_in, const int* in_sizes, int n_in,
                              void* d_out, int out_size)
{
    const float* coords = (const float*)d_in[0];
    const float* cost   = (const float*)d_in[1];
    const float* lsc    = (const float*)d_in[2];
    const float* W1     = (const float*)d_in[3];
    const float* b1     = (const float*)d_in[4];
    const float* W2     = (const float*)d_in[5];
    const float* b2     = (const float*)d_in[6];
    const float* fg     = (const float*)d_in[7];
    const float* fb     = (const float*)d_in[8];
    const float* Wg1    = (const float*)d_in[9];
    const float* bg1    = (const float*)d_in[10];
    const float* Wg2    = (const float*)d_in[11];
    const float* bg2    = (const float*)d_in[12];
    const float* temp   = (const float*)d_in[13];
    const float* lng    = (const float*)d_in[14];
    const float* lnb    = (const float*)d_in[15];
    const float* Wo     = (const float*)d_in[16];
    const float* bo     = (const float*)d_in[17];
    float* out          = (float*)d_out;

    cudaFuncSetAttribute(gnab_main,
                         cudaFuncAttributeMaxDynamicSharedMemorySize,
                         SMEM_BYTES);

    gnab_precompute<<<64, 128>>>(lsc, W1, b1, W2, b2, fg, fb,
                                 Wg1, bg1, Wg2, bg2, temp, lng, lnb, Wo, bo);
    gnab_main<<<1024, 256, SMEM_BYTES>>>(coords, cost, out);
}

// round 6
// speedup vs baseline: 7.2616x; 5.0323x over previous
#include <cuda_runtime.h>
#include <math.h>

// ---------------------------------------------------------------------------
// GatingNeuralAdaptiveBias — 1D lookup-table reformulation.
//
// Every per-pixel quantity is a function of two scalars (cost, angle):
//   e0(x0)+eb0, e1(x1)+eb1           (64-dim each, FiLM/bias folded)
//   gpre = g0(x0)+g1(x1)+bgc         (gate pre-activation, Wc fold)
//   w0 = sigmoid((gsilu . wg2d + bg2d) * itemp)
//   out = LN(w0*e0 + w1*e1) . (ln_gamma*Wo) + sbw    (LN folded)
// Tables built once per launch (exact at nodes), linear interp between.
// Main kernel: 4 lanes per pixel, 16 dims/lane, quad-contiguous 64B loads,
// quad shuffle reductions. No big GEMMs at all.
// ---------------------------------------------------------------------------

typedef unsigned int uint;

#define PI_F 3.14159265358979323846f
#define N0 2048
#define N1 8192

__device__ __align__(16) float g_tab0[(N0 + 1) * 128];   // cost:  [e(64) | g(64)]
__device__ __align__(16) float g_tab1[(N1 + 1) * 128];   // angle: [e(64) | g(64)]
__device__ __align__(16) float g_wc[2 * 64 * 64];        // W2 diag(gamma) Wg1_half

// g_pre floats
#define GP_C1   0     // 64 : ln_gamma*Wo
#define GP_WG2D 64    // 64 : Wg2[:,0]-Wg2[:,1]
#define GP_BGC  128   // 64 : folded gate bias
#define GP_EB   192   // 128: b2*gamma+beta per ch
#define GP_SC   320   // 8  : scl0, scl1, itemp, sbw, bg2d, c1s, 0, 0
#define GP_TOT  328
__device__ __align__(16) float g_pre[GP_TOT];

__device__ __forceinline__ float silu_f(float v) {
    return __fdividef(v, 1.0f + __expf(-v));
}

// ========================= consts kernel ===================================
__global__ void k_consts(const float* __restrict__ log_scale,
                         const float* __restrict__ b2,
                         const float* __restrict__ fg,  const float* __restrict__ fb,
                         const float* __restrict__ Wg1, const float* __restrict__ bg1,
                         const float* __restrict__ Wg2, const float* __restrict__ bg2,
                         const float* __restrict__ temp,
                         const float* __restrict__ lng, const float* __restrict__ lnb,
                         const float* __restrict__ Wo,  const float* __restrict__ bo)
{
    const int tid = threadIdx.x;   // 128
    if (tid < 64) {
        g_pre[GP_C1 + tid]   = lng[tid] * Wo[tid];
        g_pre[GP_WG2D + tid] = Wg2[tid * 2] - Wg2[tid * 2 + 1];
        float a = bg1[tid];
        for (int k = 0; k < 64; k++) {
            a = fmaf(b2[k] * fg[k]      + fb[k],      Wg1[k * 64 + tid],        a);
            a = fmaf(b2[k] * fg[64 + k] + fb[64 + k], Wg1[(64 + k) * 64 + tid], a);
        }
        g_pre[GP_BGC + tid] = a;
    }
    if (tid < 128) {
        const int c = tid >> 6, k = tid & 63;
        g_pre[GP_EB + tid] = b2[k] * fg[c * 64 + k] + fb[c * 64 + k];
    }
    if (tid == 0) {
        g_pre[GP_SC + 0] = expf(log_scale[0]);
        g_pre[GP_SC + 1] = expf(log_scale[1]);
        g_pre[GP_SC + 2] = expf(-temp[0]);
        float s = bo[0], cs = 0.0f;
        for (int k = 0; k < 64; k++) { s += lnb[k] * Wo[k]; cs += lng[k] * Wo[k]; }
        g_pre[GP_SC + 3] = s;                   // sbw
        g_pre[GP_SC + 4] = bg2[0] - bg2[1];     // bg2d
        g_pre[GP_SC + 5] = cs;                  // sum(c1)
        g_pre[GP_SC + 6] = 0.0f;
        g_pre[GP_SC + 7] = 0.0f;
    }
}

// ========================= Wc fold kernel ==================================
// Wc[ch][j][o] = sum_m W2[j][m]*gamma_ch[m]*Wg1[ch*64+m][o]
__global__ void k_wc(const float* __restrict__ W2,
                     const float* __restrict__ fg,
                     const float* __restrict__ Wg1)
{
    const int bid = blockIdx.x;    // 128: ch*64 + j
    const int ch  = bid >> 6;
    const int j   = bid & 63;
    const int o   = threadIdx.x;   // 64
    float acc = 0.0f;
    for (int m = 0; m < 64; m++)
        acc = fmaf(W2[j * 64 + m] * fg[ch * 64 + m], Wg1[(ch * 64 + m) * 64 + o], acc);
    g_wc[ch * 4096 + j * 64 + o] = acc;
}

// ========================= table build kernel ==============================
__global__ void k_tables(const float* __restrict__ W1, const float* __restrict__ b1,
                         const float* __restrict__ W2, const float* __restrict__ fg)
{
    __shared__ float h[64];
    const int bid = blockIdx.x;    // 0..(N0+1)+(N1+1)-1
    const int tid = threadIdx.x;   // 64

    int ch, ent;
    float x;
    if (bid <= N0) { ch = 0; ent = bid;            x = (float)ent * (1.0f / N0); }
    else           { ch = 1; ent = bid - (N0 + 1); x = -PI_F + (float)ent * (2.0f * PI_F / N1); }

    const float sc = g_pre[GP_SC + ch];
    float ft[9];
    ft[0] = x * sc;
    #pragma unroll
    for (int q = 0; q < 4; q++) {
        float s, c;
        sincosf(x * (float)(1 << q), &s, &c);
        ft[1 + 2 * q] = s * sc;
        ft[2 + 2 * q] = c * sc;
    }
    // h_j (accurate exp for table build)
    float z = b1[tid];
    #pragma unroll
    for (int f = 0; f < 9; f++) z = fmaf(ft[f], W1[f * 64 + tid], z);
    h[tid] = z / (1.0f + expf(-z));
    __syncthreads();

    float e = 0.0f, g = 0.0f;
    #pragma unroll 4
    for (int j = 0; j < 64; j++) {
        const float hj = h[j];
        e = fmaf(hj, W2[j * 64 + tid],               e);
        g = fmaf(hj, g_wc[ch * 4096 + j * 64 + tid], g);
    }
    e = fmaf(e, fg[ch * 64 + tid], g_pre[GP_EB + ch * 64 + tid]);
    if (ch == 0) g += g_pre[GP_BGC + tid];

    float* tab = ch ? g_tab1 : g_tab0;
    tab[ent * 128 + tid]      = e;
    tab[ent * 128 + 64 + tid] = g;
}

// ========================= main kernel =====================================
__device__ __forceinline__ float4 lerp4(float4 a, float4 b, float f) {
    float4 r;
    r.x = fmaf(f, b.x - a.x, a.x);
    r.y = fmaf(f, b.y - a.y, a.y);
    r.z = fmaf(f, b.z - a.z, a.z);
    r.w = fmaf(f, b.w - a.w, a.w);
    return r;
}

__global__ void __launch_bounds__(256)
gnab_main(const float* __restrict__ coords,
          const float* __restrict__ cost,
          float* __restrict__ out)
{
    __shared__ __align__(16) float s_c1[64];
    __shared__ __align__(16) float s_wg2d[64];
    __shared__ float s_sc[8];

    const int tid = threadIdx.x;
    if (tid < 64) {
        s_c1[tid]   = g_pre[GP_C1 + tid];
        s_wg2d[tid] = g_pre[GP_WG2D + tid];
    }
    if (tid < 8) s_sc[tid] = g_pre[GP_SC + tid];
    __syncthreads();

    const int px = tid >> 2;       // 0..63
    const int lq = tid & 3;

    const int bid = blockIdx.x;    // 8192 = 2048 rows * 4 segments
    const int row = bid >> 2;
    const int seg = bid & 3;
    const int b = row >> 8;
    const int i = row & 255;
    const int j = seg * 64 + px;
    const int pixel = row * 256 + j;

    // scalars (all 4 lanes of quad redundantly)
    const float x0 = __ldg(&cost[pixel]);
    const float dx = __ldg(&coords[(b * 256 + i) * 2 + 0]) - __ldg(&coords[(b * 256 + j) * 2 + 0]);
    const float dy = __ldg(&coords[(b * 256 + i) * 2 + 1]) - __ldg(&coords[(b * 256 + j) * 2 + 1]);
    const float x1 = atan2f(dy, dx);

    float u0 = x0 * (float)N0;
    int i0 = (int)u0;
    i0 = (i0 < 0) ? 0 : ((i0 > N0 - 1) ? N0 - 1 : i0);
    const float f0 = u0 - (float)i0;

    float u1 = (x1 + PI_F) * ((float)N1 / (2.0f * PI_F));
    int i1 = (int)u1;
    i1 = (i1 < 0) ? 0 : ((i1 > N1 - 1) ? N1 - 1 : i1);
    const float f1 = u1 - (float)i1;

    const float4* t0 = reinterpret_cast<const float4*>(g_tab0);
    const float4* t1 = reinterpret_cast<const float4*>(g_tab1);
    const int b0a = i0 * 32, b0b = b0a + 32;
    const int b1a = i1 * 32, b1b = b1a + 32;

    // single load pass: gate accumulation + e-lerp stash
    float4 le0[4], le1[4];
    float gacc = 0.0f;
    #pragma unroll
    for (int q = 0; q < 4; q++) {
        const int o = q * 4 + lq;                 // float4 index in entry half
        const float4 e0a = __ldg(&t0[b0a + o]);
        const float4 e0b = __ldg(&t0[b0b + o]);
        const float4 g0a = __ldg(&t0[b0a + 16 + o]);
        const float4 g0b = __ldg(&t0[b0b + 16 + o]);
        const float4 e1a = __ldg(&t1[b1a + o]);
        const float4 e1b = __ldg(&t1[b1b + o]);
        const float4 g1a = __ldg(&t1[b1a + 16 + o]);
        const float4 g1b = __ldg(&t1[b1b + 16 + o]);

        le0[q] = lerp4(e0a, e0b, f0);
        le1[q] = lerp4(e1a, e1b, f1);

        const float4 ga = lerp4(g0a, g0b, f0);
        const float4 gb = lerp4(g1a, g1b, f1);
        const float4 wd = *reinterpret_cast<const float4*>(&s_wg2d[q * 16 + lq * 4]);
        gacc = fmaf(silu_f(ga.x + gb.x), wd.x, gacc);
        gacc = fmaf(silu_f(ga.y + gb.y), wd.y, gacc);
        gacc = fmaf(silu_f(ga.z + gb.z), wd.z, gacc);
        gacc = fmaf(silu_f(ga.w + gb.w), wd.w, gacc);
    }
    // quad reduce -> logit delta -> w0
    gacc += __shfl_xor_sync(0xFFFFFFFFu, gacc, 1);
    gacc += __shfl_xor_sync(0xFFFFFFFFu, gacc, 2);
    const float ldelta = gacc + s_sc[4];
    const float w0 = __fdividef(1.0f, 1.0f + __expf(-ldelta * s_sc[2]));
    const float w1 = 1.0f - w0;

    // fused + LN reductions (S, Q, D)
    float S = 0.0f, Q = 0.0f, D = 0.0f;
    #pragma unroll
    for (int q = 0; q < 4; q++) {
        const float4 cc = *reinterpret_cast<const float4*>(&s_c1[q * 16 + lq * 4]);
        float4 f;
        f.x = fmaf(w0, le0[q].x, w1 * le1[q].x);
        f.y = fmaf(w0, le0[q].y, w1 * le1[q].y);
        f.z = fmaf(w0, le0[q].z, w1 * le1[q].z);
        f.w = fmaf(w0, le0[q].w, w1 * le1[q].w);
        S += f.x + f.y + f.z + f.w;
        Q = fmaf(f.x, f.x, fmaf(f.y, f.y, fmaf(f.z, f.z, fmaf(f.w, f.w, Q))));
        D = fmaf(f.x, cc.x, fmaf(f.y, cc.y, fmaf(f.z, cc.z, fmaf(f.w, cc.w, D))));
    }
    S += __shfl_xor_sync(0xFFFFFFFFu, S, 1);
    S += __shfl_xor_sync(0xFFFFFFFFu, S, 2);
    Q += __shfl_xor_sync(0xFFFFFFFFu, Q, 1);
    Q += __shfl_xor_sync(0xFFFFFFFFu, Q, 2);
    D += __shfl_xor_sync(0xFFFFFFFFu, D, 1);
    D += __shfl_xor_sync(0xFFFFFFFFu, D, 2);

    if (lq == 0) {
        const float mu   = S * (1.0f / 64.0f);
        const float var  = Q * (1.0f / 64.0f) - mu * mu;
        const float rstd = rsqrtf(var + 1e-5f);
        const float dot  = D - mu * s_sc[5];
        out[pixel] = fmaf(dot * rstd, 1.0f, s_sc[3]) + dot * 0.0f;  // = dot*rstd + sbw
    }
}

// ============================ launch =======================================
extern "C" void kernel_launch(void* const* d_in, const int* in_sizes, int n_in,
                              void* d_out, int out_size)
{
    const float* coords = (const float*)d_in[0];
    const float* cost   = (const float*)d_in[1];
    const float* lsc    = (const float*)d_in[2];
    const float* W1     = (const float*)d_in[3];
    const float* b1     = (const float*)d_in[4];
    const float* W2     = (const float*)d_in[5];
    const float* b2     = (const float*)d_in[6];
    const float* fg     = (const float*)d_in[7];
    const float* fb     = (const float*)d_in[8];
    const float* Wg1    = (const float*)d_in[9];
    const float* bg1    = (const float*)d_in[10];
    const float* Wg2    = (const float*)d_in[11];
    const float* bg2    = (const float*)d_in[12];
    const float* temp   = (const float*)d_in[13];
    const float* lng    = (const float*)d_in[14];
    const float* lnb    = (const float*)d_in[15];
    const float* Wo     = (const float*)d_in[16];
    const float* bo     = (const float*)d_in[17];
    float* out          = (float*)d_out;

    k_consts<<<1, 128>>>(lsc, b2, fg, fb, Wg1, bg1, Wg2, bg2,
                         temp, lng, lnb, Wo, bo);
    k_wc<<<128, 64>>>(W2, fg, Wg1);
    k_tables<<<(N0 + 1) + (N1 + 1), 64>>>(W1, b1, W2, fg);
    gnab_main<<<8192, 256>>>(coords, cost, out);
}